// round 1
// baseline (speedup 1.0000x reference)
#include <cuda_runtime.h>
#include <cuda_bf16.h>

#define MAXB 64
#define THREADS 256

// ---------------- device scratch (no allocations allowed) ----------------
__device__ unsigned g_gmax[MAXB];   // ord-encoded max z among segment==0
__device__ unsigned g_pmin[MAXB];   // ord-encoded min z among segment==1
__device__ unsigned g_zmin[MAXB];   // ord-encoded min z overall
__device__ unsigned g_zmax[MAXB];   // ord-encoded max z overall
__device__ int      g_hasg[MAXB];
__device__ int      g_hasp[MAXB];
__device__ float    g_mu[MAXB];
__device__ double   g_sum;

// order-preserving float <-> uint mapping (monotone: f1 < f2  <=>  ord(f1) < ord(f2))
__device__ __forceinline__ unsigned ordf(float f) {
    unsigned u = __float_as_uint(f);
    return (u & 0x80000000u) ? ~u : (u | 0x80000000u);
}
__device__ __forceinline__ float deordf(unsigned o) {
    unsigned u = (o & 0x80000000u) ? (o & 0x7FFFFFFFu) : ~o;
    return __uint_as_float(u);
}

// ---------------- kernel 0: reset accumulators (graph replays!) ----------------
__global__ void k_init(int B) {
    int t = blockIdx.x * blockDim.x + threadIdx.x;
    if (t < B) {
        g_gmax[t] = 0u;
        g_pmin[t] = 0xFFFFFFFFu;
        g_zmin[t] = 0xFFFFFFFFu;
        g_zmax[t] = 0u;
        g_hasg[t] = 0;
        g_hasp[t] = 0;
    }
    if (t == 0) g_sum = 0.0;
}

// ---------------- kernel 1: per-cloud z reductions ----------------
__global__ void __launch_bounds__(THREADS) k_pass1(
    const float4* __restrict__ coord4, const int4* __restrict__ seg4,
    const float*  __restrict__ coord,  const int*  __restrict__ segment,
    const int* __restrict__ offset, int n, int B)
{
    __shared__ unsigned s_gmax[MAXB], s_pmin[MAXB], s_zmin[MAXB], s_zmax[MAXB];
    __shared__ int s_hasg[MAXB], s_hasp[MAXB], s_off[MAXB];

    int t = threadIdx.x;
    for (int j = t; j < B; j += blockDim.x) {
        s_gmax[j] = 0u; s_pmin[j] = 0xFFFFFFFFu;
        s_zmin[j] = 0xFFFFFFFFu; s_zmax[j] = 0u;
        s_hasg[j] = 0; s_hasp[j] = 0;
        s_off[j]  = offset[j];
    }
    __syncthreads();

    // running state for the thread's current batch (batches are contiguous ->
    // each thread only flushes ~B times total)
    int curb = -1;
    unsigned lg = 0u, lp = 0xFFFFFFFFu, lzm = 0xFFFFFFFFu, lzx = 0u;
    int hg = 0, hp = 0;

    auto flush = [&]() {
        if (curb >= 0) {
            atomicMin(&s_zmin[curb], lzm);
            atomicMax(&s_zmax[curb], lzx);
            if (hg) { atomicMax(&s_gmax[curb], lg); s_hasg[curb] = 1; }
            if (hp) { atomicMin(&s_pmin[curb], lp); s_hasp[curb] = 1; }
        }
        lg = 0u; lp = 0xFFFFFFFFu; lzm = 0xFFFFFFFFu; lzx = 0u;
        hg = 0; hp = 0;
    };
    auto upd = [&](int i, float z, int s) {
        int b = 0;
        #pragma unroll 8
        for (int j = 0; j < B; j++) b += (i >= s_off[j]);
        if (b != curb) { flush(); curb = b; }
        unsigned o = ordf(z);
        lzm = min(lzm, o);
        lzx = max(lzx, o);
        if (s == 0) { lg = max(lg, o); hg = 1; }
        else        { lp = min(lp, o); hp = 1; }
    };

    int n4 = n >> 2;
    int stride = gridDim.x * blockDim.x;
    for (int g = blockIdx.x * blockDim.x + t; g < n4; g += stride) {
        // 4 points: z at coord[12g+2], [12g+5], [12g+8], [12g+11]
        float4 a = coord4[3 * g + 0];
        float4 b = coord4[3 * g + 1];
        float4 c = coord4[3 * g + 2];
        int4   s = seg4[g];
        int i0 = g << 2;
        upd(i0 + 0, a.z, s.x);
        upd(i0 + 1, b.y, s.y);
        upd(i0 + 2, c.x, s.z);
        upd(i0 + 3, c.w, s.w);
    }
    // scalar tail
    for (int i = (n4 << 2) + blockIdx.x * blockDim.x + t; i < n; i += stride)
        upd(i, coord[3 * i + 2], segment[i]);
    flush();

    __syncthreads();
    for (int j = t; j < B; j += blockDim.x) {
        atomicMin(&g_zmin[j], s_zmin[j]);
        atomicMax(&g_zmax[j], s_zmax[j]);
        if (s_hasg[j]) { atomicMax(&g_gmax[j], s_gmax[j]); g_hasg[j] = 1; }
        if (s_hasp[j]) { atomicMin(&g_pmin[j], s_pmin[j]); g_hasp[j] = 1; }
    }
}

// ---------------- kernel 2: mu per cloud ----------------
__global__ void k_mu(int B) {
    int t = blockIdx.x * blockDim.x + threadIdx.x;
    if (t < B) {
        float g = g_hasg[t] ? deordf(g_gmax[t]) : deordf(g_zmin[t]);
        float p = g_hasp[t] ? deordf(g_pmin[t]) : deordf(g_zmax[t]);
        g_mu[t] = g + (p - g) * 0.5f;
    }
}

// ---------------- kernel 3: focal-CE * gaussian weight, sum-reduce ----------------
__global__ void __launch_bounds__(THREADS) k_loss(
    const float4* __restrict__ pred4, const float4* __restrict__ coord4,
    const int4* __restrict__ seg4,
    const float* __restrict__ pred, const float* __restrict__ coord,
    const int* __restrict__ segment,
    const int* __restrict__ offset, int n, int B)
{
    __shared__ int   s_off[MAXB];
    __shared__ float s_mu[MAXB];
    __shared__ float s_part[THREADS / 32];

    int t = threadIdx.x;
    for (int j = t; j < B; j += blockDim.x) {
        s_off[j] = offset[j];
        s_mu[j]  = g_mu[j];
    }
    __syncthreads();

    float acc = 0.f;

    auto pointLoss = [&](int i, float p0, float p1, int s, float z) {
        int b = 0;
        #pragma unroll 8
        for (int j = 0; j < B; j++) b += (i >= s_off[j]);
        float mu = s_mu[b];
        // 2-class log-softmax: lse = max + log1p(exp(min-max))
        float mx = fmaxf(p0, p1);
        float mn = fminf(p0, p1);
        float lse = mx + log1pf(expf(mn - mx));
        float lt = (s ? p1 : p0) - lse;        // log p_t  (<= 0)
        float ptv = expf(lt);
        float om = 1.f - ptv;
        float fw = om * om;                    // focal, gamma=2, alpha=1
        float d = z - mu;
        float dd = d * d;
        float w;
        if (z <= mu) w = expf(-50.f * dd);                       // 1/(2*0.1^2)
        else         w = (d > 0.8f) ? 0.1f : expf(-3.125f * dd); // 1/(2*0.4^2)
        acc += (-lt) * fw * w;
    };

    int n4 = n >> 2;
    int stride = gridDim.x * blockDim.x;
    for (int g = blockIdx.x * blockDim.x + t; g < n4; g += stride) {
        float4 pa = pred4[2 * g + 0];   // points 4g, 4g+1
        float4 pb = pred4[2 * g + 1];   // points 4g+2, 4g+3
        float4 a = coord4[3 * g + 0];
        float4 b = coord4[3 * g + 1];
        float4 c = coord4[3 * g + 2];
        int4   s = seg4[g];
        int i0 = g << 2;
        pointLoss(i0 + 0, pa.x, pa.y, s.x, a.z);
        pointLoss(i0 + 1, pa.z, pa.w, s.y, b.y);
        pointLoss(i0 + 2, pb.x, pb.y, s.z, c.x);
        pointLoss(i0 + 3, pb.z, pb.w, s.w, c.w);
    }
    for (int i = (n4 << 2) + blockIdx.x * blockDim.x + t; i < n; i += stride)
        pointLoss(i, pred[2 * i], pred[2 * i + 1], segment[i], coord[3 * i + 2]);

    // block reduction: warp shuffle -> shared -> warp 0 -> one double atomic
    #pragma unroll
    for (int o = 16; o > 0; o >>= 1) acc += __shfl_xor_sync(0xFFFFFFFFu, acc, o);
    int warp = t >> 5, lane = t & 31;
    if (lane == 0) s_part[warp] = acc;
    __syncthreads();
    if (warp == 0) {
        float v = (lane < (THREADS / 32)) ? s_part[lane] : 0.f;
        #pragma unroll
        for (int o = 16; o > 0; o >>= 1) v += __shfl_xor_sync(0xFFFFFFFFu, v, o);
        if (lane == 0) atomicAdd(&g_sum, (double)v);
    }
}

// ---------------- kernel 4: finalize mean ----------------
__global__ void k_fin(float* out, int n) {
    out[0] = (float)(g_sum / (double)n);
}

// ---------------- launch ----------------
extern "C" void kernel_launch(void* const* d_in, const int* in_sizes, int n_in,
                              void* d_out, int out_size)
{
    const float* pred    = (const float*)d_in[0];
    const float* coord   = (const float*)d_in[1];
    const int*   segment = (const int*)d_in[2];
    const int*   offset  = (const int*)d_in[3];
    int n = in_sizes[2];       // N points
    int B = in_sizes[3];       // number of clouds
    if (B > MAXB) B = MAXB;

    int n4 = n >> 2;
    int blocks = (n4 + THREADS - 1) / THREADS;
    const int maxBlocks = 148 * 8;  // full-occupancy grid-stride
    if (blocks > maxBlocks) blocks = maxBlocks;
    if (blocks < 1) blocks = 1;

    k_init<<<1, MAXB>>>(B);
    k_pass1<<<blocks, THREADS>>>((const float4*)coord, (const int4*)segment,
                                 coord, segment, offset, n, B);
    k_mu<<<1, MAXB>>>(B);
    k_loss<<<blocks, THREADS>>>((const float4*)pred, (const float4*)coord,
                                (const int4*)segment,
                                pred, coord, segment, offset, n, B);
    k_fin<<<1, 1>>>((float*)d_out, n);
}